// round 11
// baseline (speedup 1.0000x reference)
#include <cuda_runtime.h>
#include <cstdint>

#define N_NODES 100000
#define N_EDGES 500000
#define HIDDEN 32
#define HEADS 4
#define PROJ 128
#define LN_EPS 1e-5f

// Per-node accumulator: [node][head][{Sx,Sy,Sz,T}] = 16 floats. 6.4 MB, L2-hot.
__device__ float g_acc[(size_t)N_NODES * 16];
__device__ int   g_idx64;            // 1 if edge_index is int64
__device__ float g_PJ[HIDDEN * 16];  // folded Wv@Wout (+bv@Wout): [j][h*4+{x,y,z,T}]
__device__ float g_score[HEADS * 13];// per head: M[9] row-major, L[3], C

// ---------------------------------------------------------------------------
// Setup + zero, fused. Blocks 0..70: one warp per folded coefficient
// (lane-parallel 32-length dots, shfl-reduced). Blocks 71..582: zero g_acc.
// ---------------------------------------------------------------------------
__global__ __launch_bounds__(256) void setup_kernel(
    const int* __restrict__ e32,
    const float* __restrict__ Wq, const float* __restrict__ bq,
    const float* __restrict__ Wk, const float* __restrict__ bk,
    const float* __restrict__ Wv, const float* __restrict__ bv,
    const float* __restrict__ Wout)
{
    if (blockIdx.x >= 71) {
        const int zb = blockIdx.x - 71;
        const size_t n4 = ((size_t)N_NODES * 16) / 4;
        float4* a4 = reinterpret_cast<float4*>(g_acc);
        const size_t stride = (size_t)512 * 256;
        for (size_t i = (size_t)zb * 256 + threadIdx.x; i < n4; i += stride)
            a4[i] = make_float4(0.f, 0.f, 0.f, 0.f);
        return;
    }

    const int w = blockIdx.x * 8 + (threadIdx.x >> 5);
    const int d = threadIdx.x & 31;

    if (w < 512) {
        const int j = w >> 4, k = w & 15, h = k >> 2, comp = k & 3;
        const int c = h * 32 + d;
        const float a = (comp < 3) ? Wv[comp * PROJ + c] : bv[c];
        float s = a * Wout[c * HIDDEN + j];
#pragma unroll
        for (int off = 16; off; off >>= 1) s += __shfl_xor_sync(0xFFFFFFFFu, s, off);
        if (d == 0) g_PJ[j * 16 + k] = s;
    } else if (w < 548) {
        const int u = w - 512, h = u / 9, ij = u % 9, i = ij / 3, jj = ij % 3;
        const int c = h * 32 + d;
        float s = Wq[i * PROJ + c] * Wk[jj * PROJ + c];
#pragma unroll
        for (int off = 16; off; off >>= 1) s += __shfl_xor_sync(0xFFFFFFFFu, s, off);
        if (d == 0) g_score[h * 13 + ij] = s;
    } else if (w < 560) {
        const int u = w - 548, h = u / 3, i = u % 3;
        const int c = h * 32 + d;
        float s = Wq[i * PROJ + c] * bk[c] + bq[c] * Wk[i * PROJ + c];
#pragma unroll
        for (int off = 16; off; off >>= 1) s += __shfl_xor_sync(0xFFFFFFFFu, s, off);
        if (d == 0) g_score[h * 13 + 9 + i] = s;
    } else if (w < 564) {
        const int h = w - 560;
        const int c = h * 32 + d;
        float s = bq[c] * bk[c];
#pragma unroll
        for (int off = 16; off; off >>= 1) s += __shfl_xor_sync(0xFFFFFFFFu, s, off);
        if (d == 0) g_score[h * 13 + 12] = s;
    } else if (w == 564) {
        const bool z = (e32[2 * d + 1] == 0) && (e32[2 * (d + 32) + 1] == 0);
        const int all = __all_sync(0xFFFFFFFFu, z);
        if (d == 0) g_idx64 = all;
    }
}

// ---------------------------------------------------------------------------
// Edge kernel: one thread per edge. Index/pos loads HOISTED above the smem
// staging barrier so the gather latency overlaps staging. Math unchanged.
// ---------------------------------------------------------------------------
__global__ __launch_bounds__(256) void edge_kernel(
    const float* __restrict__ pos, const void* __restrict__ eidx_raw)
{
    __shared__ float sc[HEADS * 13];
    const int tid = threadIdx.x;
    const int e = blockIdx.x * 256 + tid;
    const bool active = (e < N_EDGES);

    // --- issue global loads first (no smem dependence) ---
    int row = 0, col = 0;
    if (active) {
        if (g_idx64) {
            const long long* p = (const long long*)eidx_raw;
            row = (int)p[e];
            col = (int)p[N_EDGES + e];
        } else {
            const int* p = (const int*)eidx_raw;
            row = p[e];
            col = p[N_EDGES + e];
        }
    }
    const bool ok = active && (unsigned)row < N_NODES && (unsigned)col < N_NODES;
    float rx = 0.f, ry = 0.f, rz = 0.f;
    if (ok) {
        rx = pos[row * 3 + 0] - pos[col * 3 + 0];
        ry = pos[row * 3 + 1] - pos[col * 3 + 1];
        rz = pos[row * 3 + 2] - pos[col * 3 + 2];
    }

    // --- stage score coefficients, then sync (all threads reach this) ---
    if (tid < HEADS * 13) sc[tid] = g_score[tid];
    __syncthreads();

    if (!ok) return;

    float s[HEADS];
#pragma unroll
    for (int h = 0; h < HEADS; h++) {
        const float* m = &sc[h * 13];
        const float tx = fmaf(m[0], rx, fmaf(m[1], ry, m[2] * rz));
        const float ty = fmaf(m[3], rx, fmaf(m[4], ry, m[5] * rz));
        const float tz = fmaf(m[6], rx, fmaf(m[7], ry, m[8] * rz));
        float v = fmaf(rx, tx, fmaf(ry, ty, rz * tz));
        v += fmaf(m[9], rx, fmaf(m[10], ry, fmaf(m[11], rz, m[12])));
        s[h] = v * 0.17677669529663687f;   // 1/sqrt(32)
    }
    const float mx = fmaxf(fmaxf(s[0], s[1]), fmaxf(s[2], s[3]));
    float ex[HEADS], tot = 0.f;
#pragma unroll
    for (int h = 0; h < HEADS; h++) { ex[h] = __expf(s[h] - mx); tot += ex[h]; }
    const float inv = 1.f / tot;

    float* dst = g_acc + (size_t)col * 16;
#pragma unroll
    for (int h = 0; h < HEADS; h++) {
        const float a = ex[h] * inv;
        asm volatile("red.global.add.v4.f32 [%0], {%1,%2,%3,%4};"
                     :: "l"(dst + h * 4), "f"(a * rx), "f"(a * ry), "f"(a * rz), "f"(a)
                     : "memory");
    }
}

// ---------------------------------------------------------------------------
// Node kernel: TWO threads per node; acc loads HOISTED above the smem
// staging barrier. Each thread owns 16 outputs; pair-shfl LN reductions.
// ---------------------------------------------------------------------------
__global__ __launch_bounds__(256) void node_kernel(
    const float* __restrict__ bout, const float* __restrict__ gamma,
    const float* __restrict__ beta, float* __restrict__ out)
{
    __shared__ float sPJ[HIDDEN * 16];
    __shared__ float sb[HIDDEN], sg[HIDDEN], sbt[HIDDEN];
    const int tid = threadIdx.x;
    const int gt = blockIdx.x * 256 + tid;
    const int node = gt >> 1;
    const int half = gt & 1;
    const bool ok = (node < N_NODES);

    // --- issue acc loads first ---
    float4 a0, a1, a2, a3;
    if (ok) {
        const float4* ap = reinterpret_cast<const float4*>(g_acc + (size_t)node * 16);
        a0 = ap[0]; a1 = ap[1]; a2 = ap[2]; a3 = ap[3];
    } else {
        a0 = a1 = a2 = a3 = make_float4(0.f, 0.f, 0.f, 0.f);
    }

    // --- stage tables, then sync ---
    for (int i = tid; i < HIDDEN * 16; i += 256) sPJ[i] = g_PJ[i];
    if (tid < HIDDEN) { sb[tid] = bout[tid]; sg[tid] = gamma[tid]; sbt[tid] = beta[tid]; }
    __syncthreads();

    if (!ok) return;

    const float cnt = a0.w + a1.w + a2.w + a3.w;
    const float inv = 1.f / fmaxf(cnt, 1.f);

    const int j0 = half * 16;
    float o[16];
    float psum = 0.f;
#pragma unroll
    for (int jj = 0; jj < 16; jj++) {
        const int j = j0 + jj;
        const float4* p = reinterpret_cast<const float4*>(&sPJ[j * 16]);
        const float4 p0 = p[0], p1 = p[1], p2 = p[2], p3 = p[3];
        float dd = a0.x * p0.x + a0.y * p0.y + a0.z * p0.z + a0.w * p0.w;
        dd += a1.x * p1.x + a1.y * p1.y + a1.z * p1.z + a1.w * p1.w;
        dd += a2.x * p2.x + a2.y * p2.y + a2.z * p2.z + a2.w * p2.w;
        dd += a3.x * p3.x + a3.y * p3.y + a3.z * p3.z + a3.w * p3.w;
        o[jj] = fmaf(dd, inv, sb[j]);
        psum += o[jj];
    }
    psum += __shfl_xor_sync(0xFFFFFFFFu, psum, 1);
    const float mu = psum * (1.f / 32.f);

    float psq = 0.f;
#pragma unroll
    for (int jj = 0; jj < 16; jj++) { const float d = o[jj] - mu; psq += d * d; }
    psq += __shfl_xor_sync(0xFFFFFFFFu, psq, 1);
    const float rstd = rsqrtf(psq * (1.f / 32.f) + LN_EPS);

    float4 w4[4];
#pragma unroll
    for (int jj = 0; jj < 16; jj++) {
        const int j = j0 + jj;
        const float y = (o[jj] - mu) * rstd * sg[j] + sbt[j];
        reinterpret_cast<float*>(w4)[jj] = y / (1.f + __expf(-y));
    }
    float4* op = reinterpret_cast<float4*>(out + (size_t)node * HIDDEN + j0);
#pragma unroll
    for (int k = 0; k < 4; k++) op[k] = w4[k];
}

// ---------------------------------------------------------------------------
extern "C" void kernel_launch(void* const* d_in, const int* in_sizes, int n_in,
                              void* d_out, int out_size)
{
    const float* pos   = (const float*)d_in[0];
    const void*  eidx  = d_in[1];
    const float* Wq    = (const float*)d_in[2];
    const float* bq    = (const float*)d_in[3];
    const float* Wk    = (const float*)d_in[4];
    const float* bk    = (const float*)d_in[5];
    const float* Wv    = (const float*)d_in[6];
    const float* bv    = (const float*)d_in[7];
    const float* Wout  = (const float*)d_in[8];
    const float* bout  = (const float*)d_in[9];
    const float* gamma = (const float*)d_in[10];
    const float* beta  = (const float*)d_in[11];
    float*       out   = (float*)d_out;

    setup_kernel<<<71 + 512, 256>>>((const int*)eidx, Wq, bq, Wk, bk, Wv, bv, Wout);
    edge_kernel<<<(N_EDGES + 255) / 256, 256>>>(pos, eidx);
    node_kernel<<<(N_NODES * 2 + 255) / 256, 256>>>(bout, gamma, beta, out);
}